// round 4
// baseline (speedup 1.0000x reference)
#include <cuda_runtime.h>
#include <math.h>

#define BATCH 64
#define SEQ   2048
#define DIN   256
#define DOUT  256
#define MTOT  (BATCH * SEQ)

#define NSCAN   64
#define NWORK   84
#define NCTA    (NSCAN + NWORK)      // 148 CTAs = 1/SM, all wave-1 resident
#define CHUNK   64                   // scan flag granularity (timesteps)
#define NCHUNK  (SEQ / CHUNK)        // 32

// GEMM tiles: 128(M) x 64(N); one M-tile covers 2 chunks of one batch.
#define TILE_M   128
#define MCHUNK   (SEQ / TILE_M)      // 16 m-tiles per batch
#define NTILES   (MCHUNK * BATCH * 4)  // 4096

#define KREG 184
#define KSM  (DOUT - KREG)           // 72
#define SCAN_SMEM_BYTES ((KSM * DOUT + 2 * DOUT) * (int)sizeof(float))  // 75776

__device__ int g_flags[BATCH * NCHUNK];

__global__ void reset_flags_kernel()
{
    int i = blockIdx.x * blockDim.x + threadIdx.x;
    if (i < BATCH * NCHUNK) g_flags[i] = 0;
}

// ---------------------------------------------------------------------------
// Bit-exact replica of XLA's EmitFastTanh (Eigen fast tanh, FMA variant).
// ---------------------------------------------------------------------------
__device__ __forceinline__ float xla_tanh(float x)
{
    const float kClamp = 7.99881172180175781f;
    const float kTiny  = 0.0004f;
    const float a1  = 4.89352455891786e-03f;
    const float a3  = 6.37261928875436e-04f;
    const float a5  = 1.48572235717979e-05f;
    const float a7  = 5.12229709037114e-08f;
    const float a9  = -8.60467152213735e-11f;
    const float a11 = 2.00018790482477e-13f;
    const float a13 = -2.76076847742355e-16f;
    const float b0  = 4.89352518554385e-03f;
    const float b2  = 2.26843463243900e-03f;
    const float b4  = 1.18534705686654e-04f;
    const float b6  = 1.19825839466702e-06f;

    float ax = fabsf(x);
    float xc = fminf(fmaxf(x, -kClamp), kClamp);
    float x2 = __fmul_rn(xc, xc);

    float p = __fmaf_rn(x2, a13, a11);
    p = __fmaf_rn(x2, p, a9);
    p = __fmaf_rn(x2, p, a7);
    p = __fmaf_rn(x2, p, a5);
    p = __fmaf_rn(x2, p, a3);
    p = __fmaf_rn(x2, p, a1);
    p = __fmul_rn(xc, p);

    float q = __fmaf_rn(x2, b6, b4);
    q = __fmaf_rn(x2, q, b2);
    q = __fmaf_rn(x2, q, b0);

    float r = __fdiv_rn(p, q);
    return (ax < kTiny) ? x : r;
}

// ---------------------------------------------------------------------------
// GEMM producer branch: zx = input @ W_x + (b_x+b_h) in 128x64 tiles ordered
// by time so scan CTAs can stream behind. Single fp32 accumulator per output
// element, ascending k, fused FMA (bit-exact).
// ---------------------------------------------------------------------------
__device__ void gemm_worker(
    float* sm, int worker,
    const float* __restrict__ A,    // [MTOT][DIN]
    const float* __restrict__ W,    // [DIN][DOUT]
    const float* __restrict__ b_h,
    const float* __restrict__ b_x,
    float* __restrict__ C)          // [MTOT][DOUT]
{
    float* As   = sm;                       // [128][36]
    float* Bs   = sm + TILE_M * 36;         // [32][64]
    float* bias = sm + TILE_M * 36 + 32 * 64;

    const int tid = threadIdx.x;
    const int tx = tid & 15;                // n quad
    const int ty = tid >> 4;                // m octet

    for (int tau = worker; tau < NTILES; tau += NWORK) {
        const int mt = tau >> 8;            // m-tile 0..15 (time-ascending)
        const int r  = tau & 255;
        const int bb = r >> 2;
        const int nq = r & 3;
        const long m0 = (long)bb * SEQ + (long)mt * TILE_M;
        const int n0 = nq * 64;

        if (tid < 64) bias[tid] = __fadd_rn(b_h[n0 + tid], b_x[n0 + tid]);

        float acc[32];
#pragma unroll
        for (int i = 0; i < 32; ++i) acc[i] = 0.f;

        for (int kc = 0; kc < DIN; kc += 32) {
            __syncthreads();
            // A chunk: 128 rows x 32 k = 1024 float4 (4 per thread)
#pragma unroll
            for (int l = 0; l < 4; ++l) {
                int i = tid + l * 256;
                int rr = i >> 3, cc = (i & 7) << 2;
                float4 v = *(const float4*)(A + (m0 + rr) * DIN + kc + cc);
                As[rr * 36 + cc + 0] = v.x; As[rr * 36 + cc + 1] = v.y;
                As[rr * 36 + cc + 2] = v.z; As[rr * 36 + cc + 3] = v.w;
            }
            // B chunk: 32 k x 64 n = 512 float4 (2 per thread)
#pragma unroll
            for (int l = 0; l < 2; ++l) {
                int i = tid + l * 256;
                int kk = i >> 4, gg = (i & 15) << 2;
                *(float4*)(Bs + kk * 64 + gg) =
                    *(const float4*)(W + (kc + kk) * DOUT + n0 + gg);
            }
            __syncthreads();

#pragma unroll
            for (int k = 0; k < 32; ++k) {
                float4 b4 = *(const float4*)(Bs + k * 64 + (tx << 2));
#pragma unroll
                for (int i = 0; i < 8; ++i) {
                    float a = As[(ty * 8 + i) * 36 + k];
                    acc[i * 4 + 0] = __fmaf_rn(a, b4.x, acc[i * 4 + 0]);
                    acc[i * 4 + 1] = __fmaf_rn(a, b4.y, acc[i * 4 + 1]);
                    acc[i * 4 + 2] = __fmaf_rn(a, b4.z, acc[i * 4 + 2]);
                    acc[i * 4 + 3] = __fmaf_rn(a, b4.w, acc[i * 4 + 3]);
                }
            }
        }

#pragma unroll
        for (int i = 0; i < 8; ++i) {
            float4 o;
            o.x = __fadd_rn(acc[i * 4 + 0], bias[(tx << 2) + 0]);
            o.y = __fadd_rn(acc[i * 4 + 1], bias[(tx << 2) + 1]);
            o.z = __fadd_rn(acc[i * 4 + 2], bias[(tx << 2) + 2]);
            o.w = __fadd_rn(acc[i * 4 + 3], bias[(tx << 2) + 3]);
            *(float4*)(C + (m0 + ty * 8 + i) * DOUT + n0 + (tx << 2)) = o;
        }

        __threadfence();
        __syncthreads();
        if (tid == 0) {
            // tile spans chunks 2*mt and 2*mt+1 of batch bb
            atomicAdd(&g_flags[bb * NCHUNK + 2 * mt + 0], 1);
            atomicAdd(&g_flags[bb * NCHUNK + 2 * mt + 1], 1);
        }
    }
}

// ---------------------------------------------------------------------------
// Fused kernel: CTAs [0,64) scan one batch row each (thread j owns column j);
// CTAs [64,148) produce zx tiles.
// Scan matvec: strict single-accumulator ascending-k FMA chain with an
// explicit 2-deep hv (h float4) pipeline and 1-deep smem-weight pipeline so
// LDS latency never gates the 4-cyc FMA chain.
// ---------------------------------------------------------------------------
__global__ __launch_bounds__(256, 1) void rnn_fused_kernel(
    const float* __restrict__ input,
    const float* __restrict__ h0,
    const float* __restrict__ Wh,
    const float* __restrict__ Wx,
    const float* __restrict__ b_h,
    const float* __restrict__ b_x,
    float* __restrict__ y,
    float* __restrict__ hfin)
{
    extern __shared__ float sm[];

    if (blockIdx.x >= NSCAN) {
        gemm_worker(sm, blockIdx.x - NSCAN, input, Wx, b_h, b_x, y);
        return;
    }

    float* Ws   = sm;                 // [KSM][DOUT] rows KREG..255
    float* hbuf = sm + KSM * DOUT;    // [2][DOUT]

    const int b = blockIdx.x;
    const int j = threadIdx.x;

    float w[KREG];
#pragma unroll
    for (int kk = 0; kk < KREG; ++kk)
        w[kk] = Wh[kk * DOUT + j];

    for (int idx = j; idx < KSM * DOUT; idx += 256)
        Ws[idx] = Wh[KREG * DOUT + idx];

    hbuf[j] = h0[b * DOUT + j];
    __syncthreads();

    float* yb = y + (size_t)b * SEQ * DOUT;
    int cur = 0;

    for (int t = 0; t < SEQ; ++t) {
        if ((t & (CHUNK - 1)) == 0) {
            const int c = t / CHUNK;
            if (j == 0) {
                while (*(volatile int*)&g_flags[b * NCHUNK + c] != 4) { }
            }
            __syncthreads();
            __threadfence();          // order flag observation before zx loads
        }

        float zx = yb[(size_t)t * DOUT + j];

        const float4* h4 = (const float4*)(hbuf + cur * DOUT);
        float4 c0 = h4[0];
        float4 c1 = h4[1];
        float acc = 0.f;

        // groups 0..45: register weights, hv pipelined 2 ahead
#pragma unroll
        for (int g = 0; g < KREG / 4; ++g) {
            float4 nx = h4[g + 2];               // g+2 <= 47
            acc = __fmaf_rn(c0.x, w[4 * g + 0], acc);
            acc = __fmaf_rn(c0.y, w[4 * g + 1], acc);
            acc = __fmaf_rn(c0.z, w[4 * g + 2], acc);
            acc = __fmaf_rn(c0.w, w[4 * g + 3], acc);
            c0 = c1; c1 = nx;
        }

        // groups 46..63: smem weights, both hv and weights pipelined
        float w0 = Ws[0 * DOUT + j], w1 = Ws[1 * DOUT + j];
        float w2 = Ws[2 * DOUT + j], w3 = Ws[3 * DOUT + j];
#pragma unroll
        for (int g = 0; g < KSM / 4; ++g) {
            float4 nx = (g < KSM / 4 - 2) ? h4[g + 2 + KREG / 4] : c1;
            float n0, n1, n2, n3;
            if (g < KSM / 4 - 1) {
                n0 = Ws[(4 * g + 4) * DOUT + j];
                n1 = Ws[(4 * g + 5) * DOUT + j];
                n2 = Ws[(4 * g + 6) * DOUT + j];
                n3 = Ws[(4 * g + 7) * DOUT + j];
            }
            acc = __fmaf_rn(c0.x, w0, acc);
            acc = __fmaf_rn(c0.y, w1, acc);
            acc = __fmaf_rn(c0.z, w2, acc);
            acc = __fmaf_rn(c0.w, w3, acc);
            c0 = c1; c1 = nx;
            if (g < KSM / 4 - 1) { w0 = n0; w1 = n1; w2 = n2; w3 = n3; }
        }

        float v = xla_tanh(__fadd_rn(acc, zx));
        hbuf[(cur ^ 1) * DOUT + j] = v;
        __syncthreads();
        yb[(size_t)t * DOUT + j] = v;       // off the critical path
        cur ^= 1;
    }

    hfin[b * DOUT + j] = hbuf[cur * DOUT + j];
}

// ---------------------------------------------------------------------------
extern "C" void kernel_launch(void* const* d_in, const int* in_sizes, int n_in,
                              void* d_out, int out_size)
{
    const float* input = (const float*)d_in[0];
    const float* h0    = (const float*)d_in[1];
    const float* W_h   = (const float*)d_in[2];
    const float* W_x   = (const float*)d_in[3];
    const float* b_h   = (const float*)d_in[4];
    const float* b_x   = (const float*)d_in[5];

    float* y    = (float*)d_out;
    float* hfin = y + (size_t)BATCH * SEQ * DOUT;

    cudaFuncSetAttribute(rnn_fused_kernel,
                         cudaFuncAttributeMaxDynamicSharedMemorySize,
                         SCAN_SMEM_BYTES);

    reset_flags_kernel<<<8, 256>>>();
    rnn_fused_kernel<<<NCTA, 256, SCAN_SMEM_BYTES>>>(
        input, h0, W_h, W_x, b_h, b_x, y, hfin);
}

// round 5
// speedup vs baseline: 1.0745x; 1.0745x over previous
#include <cuda_runtime.h>
#include <math.h>

#define BATCH 64
#define SEQ   2048
#define DIN   256
#define DOUT  256
#define MTOT  (BATCH * SEQ)

#define NSCAN   64
#define NWORK   84
#define NCTA    (NSCAN + NWORK)      // 148 CTAs = one per SM
#define CHUNK   64
#define NCHUNK  (SEQ / CHUNK)        // 32
#define NTILES  (NCHUNK * BATCH * 4) // 8192 64x64 tiles

#define KREG 192
#define KSM  (DOUT - KREG)           // 64
#define SCAN_SMEM_BYTES ((KSM * DOUT + 2 * DOUT) * (int)sizeof(float))  // 67584

__device__ int g_flags[BATCH * NCHUNK];

__global__ void reset_flags_kernel()
{
    int i = blockIdx.x * blockDim.x + threadIdx.x;
    if (i < BATCH * NCHUNK) g_flags[i] = 0;
}

__device__ __forceinline__ int ld_acquire_gpu(const int* p)
{
    int v;
    asm volatile("ld.acquire.gpu.global.b32 %0, [%1];"
                 : "=r"(v) : "l"(p) : "memory");
    return v;
}

// ---------------------------------------------------------------------------
// Bit-exact replica of XLA's EmitFastTanh (Eigen fast tanh, FMA variant).
// ---------------------------------------------------------------------------
__device__ __forceinline__ float xla_tanh(float x)
{
    const float kClamp = 7.99881172180175781f;
    const float kTiny  = 0.0004f;
    const float a1  = 4.89352455891786e-03f;
    const float a3  = 6.37261928875436e-04f;
    const float a5  = 1.48572235717979e-05f;
    const float a7  = 5.12229709037114e-08f;
    const float a9  = -8.60467152213735e-11f;
    const float a11 = 2.00018790482477e-13f;
    const float a13 = -2.76076847742355e-16f;
    const float b0  = 4.89352518554385e-03f;
    const float b2  = 2.26843463243900e-03f;
    const float b4  = 1.18534705686654e-04f;
    const float b6  = 1.19825839466702e-06f;

    float ax = fabsf(x);
    float xc = fminf(fmaxf(x, -kClamp), kClamp);
    float x2 = __fmul_rn(xc, xc);

    float p = __fmaf_rn(x2, a13, a11);
    p = __fmaf_rn(x2, p, a9);
    p = __fmaf_rn(x2, p, a7);
    p = __fmaf_rn(x2, p, a5);
    p = __fmaf_rn(x2, p, a3);
    p = __fmaf_rn(x2, p, a1);
    p = __fmul_rn(xc, p);

    float q = __fmaf_rn(x2, b6, b4);
    q = __fmaf_rn(x2, q, b2);
    q = __fmaf_rn(x2, q, b0);

    float r = __fdiv_rn(p, q);
    return (ax < kTiny) ? x : r;
}

// ---------------------------------------------------------------------------
// GEMM producer: zx = input @ W_x + (b_x+b_h), 64x64 tiles in time order.
// Streaming cache hints (ldcs/stcs) keep L2 clean for the scan consumers.
// Bit-exact: single fp32 accumulator, ascending k, fused FMA.
// ---------------------------------------------------------------------------
__device__ void gemm_worker(
    float* sm, int worker,
    const float* __restrict__ A,
    const float* __restrict__ W,
    const float* __restrict__ b_h,
    const float* __restrict__ b_x,
    float* __restrict__ C)
{
    float* As   = sm;                // [64][36]
    float* Bs   = sm + 64 * 36;      // [32][64]
    float* bias = sm + 64 * 36 + 32 * 64;

    const int tid = threadIdx.x;
    const int tx = tid & 15;
    const int ty = tid >> 4;

    for (int tau = worker; tau < NTILES; tau += NWORK) {
        const int c  = tau >> 8;          // chunk, ascending in time
        const int r  = tau & 255;
        const int bb = r >> 2;
        const int nq = r & 3;
        const long m0 = (long)bb * SEQ + (long)c * CHUNK;
        const int n0 = nq * 64;

        if (tid < 64) bias[tid] = __fadd_rn(b_h[n0 + tid], b_x[n0 + tid]);

        float acc[16];
#pragma unroll
        for (int i = 0; i < 16; ++i) acc[i] = 0.f;

        for (int kc = 0; kc < DIN; kc += 32) {
            __syncthreads();
            {
                int i0 = tid, i1 = tid + 256;
                int r0 = i0 >> 3, c0 = (i0 & 7) << 2;
                int r1 = i1 >> 3, c1 = (i1 & 7) << 2;
                float4 v0 = __ldcs((const float4*)(A + (m0 + r0) * DIN + kc + c0));
                float4 v1 = __ldcs((const float4*)(A + (m0 + r1) * DIN + kc + c1));
                As[r0 * 36 + c0 + 0] = v0.x; As[r0 * 36 + c0 + 1] = v0.y;
                As[r0 * 36 + c0 + 2] = v0.z; As[r0 * 36 + c0 + 3] = v0.w;
                As[r1 * 36 + c1 + 0] = v1.x; As[r1 * 36 + c1 + 1] = v1.y;
                As[r1 * 36 + c1 + 2] = v1.z; As[r1 * 36 + c1 + 3] = v1.w;
            }
            {
                int i0 = tid, i1 = tid + 256;
                int k0 = i0 >> 4, g0 = (i0 & 15) << 2;
                int k1 = i1 >> 4, g1 = (i1 & 15) << 2;
                *(float4*)(Bs + k0 * 64 + g0) =
                    *(const float4*)(W + (kc + k0) * DOUT + n0 + g0);
                *(float4*)(Bs + k1 * 64 + g1) =
                    *(const float4*)(W + (kc + k1) * DOUT + n0 + g1);
            }
            __syncthreads();

#pragma unroll
            for (int k = 0; k < 32; ++k) {
                float4 b4 = *(const float4*)(Bs + k * 64 + (tx << 2));
                float a0 = As[(ty * 4 + 0) * 36 + k];
                float a1 = As[(ty * 4 + 1) * 36 + k];
                float a2 = As[(ty * 4 + 2) * 36 + k];
                float a3 = As[(ty * 4 + 3) * 36 + k];
                acc[ 0] = __fmaf_rn(a0, b4.x, acc[ 0]);
                acc[ 1] = __fmaf_rn(a0, b4.y, acc[ 1]);
                acc[ 2] = __fmaf_rn(a0, b4.z, acc[ 2]);
                acc[ 3] = __fmaf_rn(a0, b4.w, acc[ 3]);
                acc[ 4] = __fmaf_rn(a1, b4.x, acc[ 4]);
                acc[ 5] = __fmaf_rn(a1, b4.y, acc[ 5]);
                acc[ 6] = __fmaf_rn(a1, b4.z, acc[ 6]);
                acc[ 7] = __fmaf_rn(a1, b4.w, acc[ 7]);
                acc[ 8] = __fmaf_rn(a2, b4.x, acc[ 8]);
                acc[ 9] = __fmaf_rn(a2, b4.y, acc[ 9]);
                acc[10] = __fmaf_rn(a2, b4.z, acc[10]);
                acc[11] = __fmaf_rn(a2, b4.w, acc[11]);
                acc[12] = __fmaf_rn(a3, b4.x, acc[12]);
                acc[13] = __fmaf_rn(a3, b4.y, acc[13]);
                acc[14] = __fmaf_rn(a3, b4.z, acc[14]);
                acc[15] = __fmaf_rn(a3, b4.w, acc[15]);
            }
        }

#pragma unroll
        for (int i = 0; i < 4; ++i) {
            float4 o;
            o.x = __fadd_rn(acc[i * 4 + 0], bias[(tx << 2) + 0]);
            o.y = __fadd_rn(acc[i * 4 + 1], bias[(tx << 2) + 1]);
            o.z = __fadd_rn(acc[i * 4 + 2], bias[(tx << 2) + 2]);
            o.w = __fadd_rn(acc[i * 4 + 3], bias[(tx << 2) + 3]);
            __stcs((float4*)(C + (m0 + ty * 4 + i) * DOUT + n0 + (tx << 2)), o);
        }

        __threadfence();        // release: make tile visible before flag bump
        __syncthreads();
        if (tid == 0) atomicAdd(&g_flags[bb * NCHUNK + c], 1);
    }
}

// ---------------------------------------------------------------------------
// Fused kernel. CTAs [0,64): scan one batch row (thread j = column j).
// Scan matvec: strict single-accumulator ascending-k FMA chain (bit-exact),
// ptxas-scheduled (round-2 proven config). Chunk handshake happens 16 steps
// EARLY (overlapped with compute) via one acquire load on thread 0.
// ---------------------------------------------------------------------------
__global__ __launch_bounds__(256, 1) void rnn_fused_kernel(
    const float* __restrict__ input,
    const float* __restrict__ h0,
    const float* __restrict__ Wh,
    const float* __restrict__ Wx,
    const float* __restrict__ b_h,
    const float* __restrict__ b_x,
    float* __restrict__ y,
    float* __restrict__ hfin)
{
    extern __shared__ float sm[];

    if (blockIdx.x >= NSCAN) {
        gemm_worker(sm, blockIdx.x - NSCAN, input, Wx, b_h, b_x, y);
        return;
    }

    float* Ws   = sm;                 // [KSM][DOUT]
    float* hbuf = sm + KSM * DOUT;    // [2][DOUT]

    const int b = blockIdx.x;
    const int j = threadIdx.x;

    float w[KREG];
#pragma unroll
    for (int kk = 0; kk < KREG; ++kk)
        w[kk] = Wh[kk * DOUT + j];

    for (int idx = j; idx < KSM * DOUT; idx += 256)
        Ws[idx] = Wh[KREG * DOUT + idx];

    hbuf[j] = h0[b * DOUT + j];

    // Wait for chunk 0 before the first zx load.
    if (j == 0) {
        while (ld_acquire_gpu(&g_flags[b * NCHUNK + 0]) != 4) { }
    }
    __syncthreads();

    float* yb = y + (size_t)b * SEQ * DOUT;
    int cur = 0;

    for (int t = 0; t < SEQ; ++t) {
        // Overlapped handshake: 16 steps before a chunk boundary, thread 0
        // acquires the NEXT chunk's flag. Producer is normally far ahead, so
        // this is one L2 load; ordering to other threads comes from the
        // per-step __syncthreads below.
        if ((t & (CHUNK - 1)) == CHUNK - 16) {
            const int cnext = (t >> 6) + 1;
            if (cnext < NCHUNK && j == 0) {
                while (ld_acquire_gpu(&g_flags[b * NCHUNK + cnext]) != 4) { }
            }
        }

        float zx = yb[(size_t)t * DOUT + j];

        const float4* h4 = (const float4*)(hbuf + cur * DOUT);
        float acc = 0.f;

#pragma unroll
        for (int kk = 0; kk < KREG; kk += 4) {
            float4 hv = h4[kk >> 2];
            acc = __fmaf_rn(hv.x, w[kk + 0], acc);
            acc = __fmaf_rn(hv.y, w[kk + 1], acc);
            acc = __fmaf_rn(hv.z, w[kk + 2], acc);
            acc = __fmaf_rn(hv.w, w[kk + 3], acc);
        }
#pragma unroll
        for (int kk = 0; kk < KSM; kk += 4) {
            float4 hv = h4[(KREG + kk) >> 2];
            acc = __fmaf_rn(hv.x, Ws[(kk + 0) * DOUT + j], acc);
            acc = __fmaf_rn(hv.y, Ws[(kk + 1) * DOUT + j], acc);
            acc = __fmaf_rn(hv.z, Ws[(kk + 2) * DOUT + j], acc);
            acc = __fmaf_rn(hv.w, Ws[(kk + 3) * DOUT + j], acc);
        }

        float v = xla_tanh(__fadd_rn(acc, zx));
        hbuf[(cur ^ 1) * DOUT + j] = v;
        __syncthreads();
        __stcs(&yb[(size_t)t * DOUT + j], v);   // off the critical path
        cur ^= 1;
    }

    hfin[b * DOUT + j] = hbuf[cur * DOUT + j];
}

// ---------------------------------------------------------------------------
extern "C" void kernel_launch(void* const* d_in, const int* in_sizes, int n_in,
                              void* d_out, int out_size)
{
    const float* input = (const float*)d_in[0];
    const float* h0    = (const float*)d_in[1];
    const float* W_h   = (const float*)d_in[2];
    const float* W_x   = (const float*)d_in[3];
    const float* b_h   = (const float*)d_in[4];
    const float* b_x   = (const float*)d_in[5];

    float* y    = (float*)d_out;
    float* hfin = y + (size_t)BATCH * SEQ * DOUT;

    cudaFuncSetAttribute(rnn_fused_kernel,
                         cudaFuncAttributeMaxDynamicSharedMemorySize,
                         SCAN_SMEM_BYTES);

    reset_flags_kernel<<<8, 256>>>();
    rnn_fused_kernel<<<NCTA, 256, SCAN_SMEM_BYTES>>>(
        input, h0, W_h, W_x, b_h, b_x, y, hfin);
}

// round 6
// speedup vs baseline: 1.1556x; 1.0755x over previous
#include <cuda_runtime.h>
#include <math.h>

#define BATCH 64
#define SEQ   2048
#define DIN   256
#define DOUT  256
#define MTOT  (BATCH * SEQ)

#define NSCAN   64
#define NWORK   84
#define NCTA    (NSCAN + NWORK)      // 148 CTAs = one per SM
#define CHUNK   64
#define NCHUNK  (SEQ / CHUNK)        // 32
#define NTILES  (NCHUNK * BATCH * 4) // 8192 64x64 tiles

#define KREG 192
#define KSM  (DOUT - KREG)           // 64
#define WSTRIDE 68                   // floats per column in WsT (272B, 16B-aligned)
// smem: WsT [DOUT][WSTRIDE] + hbuf [2][DOUT]
#define SCAN_SMEM_BYTES ((DOUT * WSTRIDE + 2 * DOUT) * (int)sizeof(float))  // 71680

__device__ int g_flags[BATCH * NCHUNK];

__global__ void reset_flags_kernel()
{
    int i = blockIdx.x * blockDim.x + threadIdx.x;
    if (i < BATCH * NCHUNK) g_flags[i] = 0;
}

__device__ __forceinline__ int ld_acquire_gpu(const int* p)
{
    int v;
    asm volatile("ld.acquire.gpu.global.b32 %0, [%1];"
                 : "=r"(v) : "l"(p) : "memory");
    return v;
}

// ---------------------------------------------------------------------------
// Bit-exact replica of XLA's EmitFastTanh (Eigen fast tanh, FMA variant).
// ---------------------------------------------------------------------------
__device__ __forceinline__ float xla_tanh(float x)
{
    const float kClamp = 7.99881172180175781f;
    const float kTiny  = 0.0004f;
    const float a1  = 4.89352455891786e-03f;
    const float a3  = 6.37261928875436e-04f;
    const float a5  = 1.48572235717979e-05f;
    const float a7  = 5.12229709037114e-08f;
    const float a9  = -8.60467152213735e-11f;
    const float a11 = 2.00018790482477e-13f;
    const float a13 = -2.76076847742355e-16f;
    const float b0  = 4.89352518554385e-03f;
    const float b2  = 2.26843463243900e-03f;
    const float b4  = 1.18534705686654e-04f;
    const float b6  = 1.19825839466702e-06f;

    float ax = fabsf(x);
    float xc = fminf(fmaxf(x, -kClamp), kClamp);
    float x2 = __fmul_rn(xc, xc);

    float p = __fmaf_rn(x2, a13, a11);
    p = __fmaf_rn(x2, p, a9);
    p = __fmaf_rn(x2, p, a7);
    p = __fmaf_rn(x2, p, a5);
    p = __fmaf_rn(x2, p, a3);
    p = __fmaf_rn(x2, p, a1);
    p = __fmul_rn(xc, p);

    float q = __fmaf_rn(x2, b6, b4);
    q = __fmaf_rn(x2, q, b2);
    q = __fmaf_rn(x2, q, b0);

    float r = __fdiv_rn(p, q);
    return (ax < kTiny) ? x : r;
}

// ---------------------------------------------------------------------------
// GEMM producer: zx = input @ W_x + (b_x+b_h), 64x64 tiles in time order.
// Bit-exact: single fp32 accumulator, ascending k, fused FMA.
// ---------------------------------------------------------------------------
__device__ void gemm_worker(
    float* sm, int worker,
    const float* __restrict__ A,
    const float* __restrict__ W,
    const float* __restrict__ b_h,
    const float* __restrict__ b_x,
    float* __restrict__ C)
{
    float* As   = sm;                // [64][36]
    float* Bs   = sm + 64 * 36;      // [32][64]
    float* bias = sm + 64 * 36 + 32 * 64;

    const int tid = threadIdx.x;
    const int tx = tid & 15;
    const int ty = tid >> 4;

    for (int tau = worker; tau < NTILES; tau += NWORK) {
        const int c  = tau >> 8;
        const int r  = tau & 255;
        const int bb = r >> 2;
        const int nq = r & 3;
        const long m0 = (long)bb * SEQ + (long)c * CHUNK;
        const int n0 = nq * 64;

        if (tid < 64) bias[tid] = __fadd_rn(b_h[n0 + tid], b_x[n0 + tid]);

        float acc[16];
#pragma unroll
        for (int i = 0; i < 16; ++i) acc[i] = 0.f;

        for (int kc = 0; kc < DIN; kc += 32) {
            __syncthreads();
            {
                int i0 = tid, i1 = tid + 256;
                int r0 = i0 >> 3, c0 = (i0 & 7) << 2;
                int r1 = i1 >> 3, c1 = (i1 & 7) << 2;
                float4 v0 = __ldcs((const float4*)(A + (m0 + r0) * DIN + kc + c0));
                float4 v1 = __ldcs((const float4*)(A + (m0 + r1) * DIN + kc + c1));
                As[r0 * 36 + c0 + 0] = v0.x; As[r0 * 36 + c0 + 1] = v0.y;
                As[r0 * 36 + c0 + 2] = v0.z; As[r0 * 36 + c0 + 3] = v0.w;
                As[r1 * 36 + c1 + 0] = v1.x; As[r1 * 36 + c1 + 1] = v1.y;
                As[r1 * 36 + c1 + 2] = v1.z; As[r1 * 36 + c1 + 3] = v1.w;
            }
            {
                int i0 = tid, i1 = tid + 256;
                int k0 = i0 >> 4, g0 = (i0 & 15) << 2;
                int k1 = i1 >> 4, g1 = (i1 & 15) << 2;
                *(float4*)(Bs + k0 * 64 + g0) =
                    *(const float4*)(W + (kc + k0) * DOUT + n0 + g0);
                *(float4*)(Bs + k1 * 64 + g1) =
                    *(const float4*)(W + (kc + k1) * DOUT + n0 + g1);
            }
            __syncthreads();

#pragma unroll
            for (int k = 0; k < 32; ++k) {
                float4 b4 = *(const float4*)(Bs + k * 64 + (tx << 2));
                float a0 = As[(ty * 4 + 0) * 36 + k];
                float a1 = As[(ty * 4 + 1) * 36 + k];
                float a2 = As[(ty * 4 + 2) * 36 + k];
                float a3 = As[(ty * 4 + 3) * 36 + k];
                acc[ 0] = __fmaf_rn(a0, b4.x, acc[ 0]);
                acc[ 1] = __fmaf_rn(a0, b4.y, acc[ 1]);
                acc[ 2] = __fmaf_rn(a0, b4.z, acc[ 2]);
                acc[ 3] = __fmaf_rn(a0, b4.w, acc[ 3]);
                acc[ 4] = __fmaf_rn(a1, b4.x, acc[ 4]);
                acc[ 5] = __fmaf_rn(a1, b4.y, acc[ 5]);
                acc[ 6] = __fmaf_rn(a1, b4.z, acc[ 6]);
                acc[ 7] = __fmaf_rn(a1, b4.w, acc[ 7]);
                acc[ 8] = __fmaf_rn(a2, b4.x, acc[ 8]);
                acc[ 9] = __fmaf_rn(a2, b4.y, acc[ 9]);
                acc[10] = __fmaf_rn(a2, b4.z, acc[10]);
                acc[11] = __fmaf_rn(a2, b4.w, acc[11]);
                acc[12] = __fmaf_rn(a3, b4.x, acc[12]);
                acc[13] = __fmaf_rn(a3, b4.y, acc[13]);
                acc[14] = __fmaf_rn(a3, b4.z, acc[14]);
                acc[15] = __fmaf_rn(a3, b4.w, acc[15]);
            }
        }

#pragma unroll
        for (int i = 0; i < 4; ++i) {
            float4 o;
            o.x = __fadd_rn(acc[i * 4 + 0], bias[(tx << 2) + 0]);
            o.y = __fadd_rn(acc[i * 4 + 1], bias[(tx << 2) + 1]);
            o.z = __fadd_rn(acc[i * 4 + 2], bias[(tx << 2) + 2]);
            o.w = __fadd_rn(acc[i * 4 + 3], bias[(tx << 2) + 3]);
            __stcs((float4*)(C + (m0 + ty * 4 + i) * DOUT + n0 + (tx << 2)), o);
        }

        __threadfence();
        __syncthreads();
        if (tid == 0) atomicAdd(&g_flags[bb * NCHUNK + c], 1);
    }
}

// ---------------------------------------------------------------------------
// Fused kernel. Scan CTAs [0,64): thread j owns column j.
// - Ws transposed per-column (WsT[j*68+i]) -> 16 LDS.128 instead of 64 LDS.32
// - chunk-outer / step-inner loops: the flag spin sits at chunk boundaries,
//   the 64-step inner loop has no data-dependent branch.
// Strict single-accumulator ascending-k FMA chain (bit-exact).
// ---------------------------------------------------------------------------
__global__ __launch_bounds__(256, 1) void rnn_fused_kernel(
    const float* __restrict__ input,
    const float* __restrict__ h0,
    const float* __restrict__ Wh,
    const float* __restrict__ Wx,
    const float* __restrict__ b_h,
    const float* __restrict__ b_x,
    float* __restrict__ y,
    float* __restrict__ hfin)
{
    extern __shared__ float sm[];

    if (blockIdx.x >= NSCAN) {
        gemm_worker(sm, blockIdx.x - NSCAN, input, Wx, b_h, b_x, y);
        return;
    }

    float* WsT  = sm;                     // [DOUT][WSTRIDE]
    float* hbuf = sm + DOUT * WSTRIDE;    // [2][DOUT]

    const int b = blockIdx.x;
    const int j = threadIdx.x;

    float w[KREG];
#pragma unroll
    for (int kk = 0; kk < KREG; ++kk)
        w[kk] = Wh[kk * DOUT + j];

    // Column-j KSM weights, contiguous: WsT[j*WSTRIDE + i] = Wh[KREG+i][j].
    // Global reads coalesced across j for each i.
#pragma unroll
    for (int i = 0; i < KSM; ++i)
        WsT[j * WSTRIDE + i] = Wh[(KREG + i) * DOUT + j];

    hbuf[j] = h0[b * DOUT + j];

    float* yb = y + (size_t)b * SEQ * DOUT;
    const float4* wt4 = (const float4*)(WsT + j * WSTRIDE);
    int cur = 0;

    for (int c = 0; c < NCHUNK; ++c) {
        // Chunk gate: after chunk 0 the producer is far ahead -> single load.
        if (j == 0) {
            while (ld_acquire_gpu(&g_flags[b * NCHUNK + c]) != 4) { }
        }
        __syncthreads();

#pragma unroll 1
        for (int ti = 0; ti < CHUNK; ++ti) {
            const int t = c * CHUNK + ti;
            float zx = yb[(size_t)t * DOUT + j];

            const float4* h4 = (const float4*)(hbuf + cur * DOUT);
            float acc = 0.f;

#pragma unroll
            for (int kk = 0; kk < KREG; kk += 4) {
                float4 hv = h4[kk >> 2];
                acc = __fmaf_rn(hv.x, w[kk + 0], acc);
                acc = __fmaf_rn(hv.y, w[kk + 1], acc);
                acc = __fmaf_rn(hv.z, w[kk + 2], acc);
                acc = __fmaf_rn(hv.w, w[kk + 3], acc);
            }
#pragma unroll
            for (int g = 0; g < KSM / 4; ++g) {
                float4 hv = h4[(KREG >> 2) + g];
                float4 wv = wt4[g];
                acc = __fmaf_rn(hv.x, wv.x, acc);
                acc = __fmaf_rn(hv.y, wv.y, acc);
                acc = __fmaf_rn(hv.z, wv.z, acc);
                acc = __fmaf_rn(hv.w, wv.w, acc);
            }

            float v = xla_tanh(__fadd_rn(acc, zx));
            hbuf[(cur ^ 1) * DOUT + j] = v;
            __syncthreads();
            __stcs(&yb[(size_t)t * DOUT + j], v);
            cur ^= 1;
        }
    }

    hfin[b * DOUT + j] = hbuf[cur * DOUT + j];
}

// ---------------------------------------------------------------------------
extern "C" void kernel_launch(void* const* d_in, const int* in_sizes, int n_in,
                              void* d_out, int out_size)
{
    const float* input = (const float*)d_in[0];
    const float* h0    = (const float*)d_in[1];
    const float* W_h   = (const float*)d_in[2];
    const float* W_x   = (const float*)d_in[3];
    const float* b_h   = (const float*)d_in[4];
    const float* b_x   = (const float*)d_in[5];

    float* y    = (float*)d_out;
    float* hfin = y + (size_t)BATCH * SEQ * DOUT;

    cudaFuncSetAttribute(rnn_fused_kernel,
                         cudaFuncAttributeMaxDynamicSharedMemorySize,
                         SCAN_SMEM_BYTES);

    reset_flags_kernel<<<8, 256>>>();
    rnn_fused_kernel<<<NCTA, 256, SCAN_SMEM_BYTES>>>(
        input, h0, W_h, W_x, b_h, b_x, y, hfin);
}